// round 14
// baseline (speedup 1.0000x reference)
#include <cuda_runtime.h>
#include <cuda_fp16.h>
#include <cuda_bf16.h>
#include <cstdint>

#define NB   16384
#define NE   8
#define DIN  900
#define DM   512
#define DSEL 128
#define EPSF 1e-9f

#define KP     928            // 58 * 16, zero-padded K
#define NSUP   29             // super k-steps of K=32
#define NSTG   4              // super-stage pipeline depth
#define SSTAGE 16384          // bytes per super-stage (2 subs x 8KB)
#define SUB    8192           // per 16-K sub-block: a1 2KB | a2 2KB | b 4KB
#define A1OFF  0
#define A2OFF  2048
#define BOFF   4096
#define DYNSM  (NSTG * SSTAGE) // 65536

#define OUT_GUIDE (NB * DM)
#define OUT_SEL   (NB * DM + 1)

__device__ float g_scratch[(size_t)2 * NB * DM];     // gated per-(token,slot) outputs
__device__ int   g_bucket[NE * NB];
__device__ int   g_count[NE];                        // zero-init at load; combine resets
__device__ float g_gate[2 * NB];
__device__ float g_iw[NB * NE];                      // inactive-mixture weights
__device__ float g_partial[512];
__device__ __half g_Xh1[(size_t)NB * KP];            // X fp16 hi limb
__device__ __half g_Xh2[(size_t)NB * KP];            // X fp16 lo limb
__device__ __half g_Wh[(size_t)NE * DM * KP];        // W transposed [e][n][k], fp16

// ---------------------------------------------------------------------------
__device__ __forceinline__ uint32_t smem_u32(const void* p) {
    return (uint32_t)__cvta_generic_to_shared(p);
}
__device__ __forceinline__ void cp16(uint32_t s, const void* g) {
    asm volatile("cp.async.cg.shared.global [%0], [%1], 16;" :: "r"(s), "l"(g));
}
__device__ __forceinline__ void cp_commit() {
    asm volatile("cp.async.commit_group;" ::: "memory");
}
template <int N>
__device__ __forceinline__ void cp_wait() {
    asm volatile("cp.async.wait_group %0;" :: "n"(N) : "memory");
}
__device__ __forceinline__ void ldm_x4(uint32_t* r, uint32_t a) {
    asm volatile("ldmatrix.sync.aligned.m8n8.x4.shared.b16 {%0,%1,%2,%3}, [%4];"
                 : "=r"(r[0]), "=r"(r[1]), "=r"(r[2]), "=r"(r[3]) : "r"(a));
}
#define MMA_F16(acc, a, b) \
    asm volatile("mma.sync.aligned.m16n8k16.row.col.f32.f16.f16.f32 " \
        "{%0,%1,%2,%3}, {%4,%5,%6,%7}, {%8,%9}, {%0,%1,%2,%3};" \
        : "+f"((acc)[0]), "+f"((acc)[1]), "+f"((acc)[2]), "+f"((acc)[3]) \
        : "r"((a)[0]), "r"((a)[1]), "r"((a)[2]), "r"((a)[3]), \
          "r"((b)[0]), "r"((b)[1]))

// swizzled offset for (row, chunk16) in a Nx32B array: kills LDSM conflicts
__device__ __forceinline__ uint32_t swz(int row, int chunk) {
    return (uint32_t)(row * 32 + (chunk ^ ((row >> 2) & 1)) * 16);
}

// ---------------------------------------------------------------------------
// Phase A lite: softmax, gates, top-2, bucketing, guide partials.
__global__ void __launch_bounds__(1024) phaseA_kernel(
    const float* __restrict__ logits,
    const int*   __restrict__ masks)
{
    __shared__ int   lcount[NE];
    __shared__ int   lbase[NE];
    __shared__ int   staging[NE][32];
    __shared__ float warpS[32];

    int tid  = threadIdx.x;
    int warp = tid >> 5;
    int lane = tid & 31;
    if (tid < NE) lcount[tid] = 0;
    __syncthreads();

    int b = blockIdx.x * 32 + warp;

    float raw[NE];
    float mx = -1e30f;
#pragma unroll
    for (int e = 0; e < NE; e++) { raw[e] = logits[b * NE + e]; mx = fmaxf(mx, raw[e]); }
    float sum = 0.f;
#pragma unroll
    for (int e = 0; e < NE; e++) { raw[e] = expf(raw[e] - mx); sum += raw[e]; }
    float inv = 1.f / sum;
    int m[NE];
#pragma unroll
    for (int e = 0; e < NE; e++) { raw[e] *= inv; m[e] = masks[b * NE + e]; }

    float w[NE]; float isum = 0.f;
#pragma unroll
    for (int e = 0; e < NE; e++) { w[e] = (m[e] == 1) ? 0.f : raw[e]; isum += w[e]; }
    float winv = 1.f / (isum + EPSF);

    float a[NE]; float srow = 0.f;
#pragma unroll
    for (int e = 0; e < NE; e++) {
        w[e] *= winv;
        a[e] = (m[e] == 1) ? raw[e] : 0.f;
        srow += a[e];
    }

    float v1 = -1.f, v2 = -1.f; int e1 = 0, e2 = 0;
#pragma unroll
    for (int e = 0; e < NE; e++) {
        if (a[e] > v1) { v2 = v1; e2 = e1; v1 = a[e]; e1 = e; }
        else if (a[e] > v2) { v2 = a[e]; e2 = e; }
    }
    float gs = 1.f / (v1 + v2 + EPSF);
    float g1 = v1 * gs, g2 = v2 * gs;

    if (lane == 0) {
#pragma unroll
        for (int e = 0; e < NE; e++) g_iw[b * NE + e] = w[e];
        g_gate[2 * b]     = g1;
        g_gate[2 * b + 1] = g2;
        if (g1 > 0.f) { int p = atomicAdd(&lcount[e1], 1); staging[e1][p] = 2 * b; }
        if (g2 > 0.f) { int p = atomicAdd(&lcount[e2], 1); staging[e2][p] = 2 * b + 1; }
        warpS[warp] = srow;
    }
    __syncthreads();
    if (tid < NE) lbase[tid] = atomicAdd(&g_count[tid], lcount[tid]);
    if (tid == 0) {
        float s = 0.f;
        for (int i = 0; i < 32; i++) s += warpS[i];
        g_partial[blockIdx.x] = s;
    }
    __syncthreads();
#pragma unroll
    for (int e = 0; e < NE; e++) {
        for (int i = tid; i < lcount[e]; i += blockDim.x)
            g_bucket[e * NB + lbase[e] + i] = staging[e][i];
    }
}

// ---------------------------------------------------------------------------
// Split X into fp16 hi/lo limbs (x = x1 + x2, ~22 bits), pad K to 928.
__global__ void split_x_kernel(const float* __restrict__ X) {
    size_t i = (size_t)blockIdx.x * blockDim.x + threadIdx.x;
    if (i >= (size_t)NB * KP) return;
    int b = (int)(i / KP), k = (int)(i % KP);
    float v = (k < DIN) ? X[(size_t)b * DIN + k] : 0.f;
    __half h = __float2half(v);
    g_Xh1[i] = h;
    g_Xh2[i] = __float2half(v - __half2float(h));
}

// ---------------------------------------------------------------------------
// Transpose W[e][k][n] -> [e][n][kpad] single fp16 limb.
__global__ void split_w_kernel(const float* __restrict__ W) {
    __shared__ float tile[32][33];
    int e = blockIdx.z;
    int k0 = blockIdx.x * 32;
    int n0 = blockIdx.y * 32;
    int tx = threadIdx.x, ty = threadIdx.y;
#pragma unroll
    for (int i = 0; i < 4; i++) {
        int k = k0 + ty + i * 8;
        tile[ty + i * 8][tx] = (k < DIN) ? W[((size_t)e * DIN + k) * DM + n0 + tx] : 0.f;
    }
    __syncthreads();
#pragma unroll
    for (int i = 0; i < 4; i++) {
        int n = n0 + ty + i * 8;
        int kk = k0 + tx;
        if (kk < KP) {
            g_Wh[((size_t)e * DM + n) * KP + kk] = __float2half(tile[tx][ty + i * 8]);
        }
    }
}

// ---------------------------------------------------------------------------
// Tensor-core grouped GEMM: mma.sync fp16, 2-pass X-limb split.
// CTA tile 64(m) x 128(n), 8 warps (2m x 4n of 32x32 tiles), acc=32 regs ->
// 3 CTAs/SM (6 warps/SMSP). Super-stage BK=32, 4-stage pipeline, one barrier
// per 32-K, XOR-swizzled dense 32B rows.
extern __shared__ char sm_dyn[];

__global__ void __launch_bounds__(256, 3) gemm_kernel(
    const float* __restrict__ bias)
{
    int e   = blockIdx.z;
    int cnt = g_count[e];
    int rt0 = blockIdx.x * 64;
    if (rt0 >= cnt) return;
    int rows = cnt - rt0; if (rows > 64) rows = 64;
    int n0 = blockIdx.y * 128;

    __shared__ int   sEntry[64];
    __shared__ float sGate[64];
    __shared__ float sBias[128];

    int t = threadIdx.x;
    int wid = t >> 5, lane = t & 31;
    int wm = wid & 1, wn = wid >> 1;       // 2m x 4n warp grid, 32x32 tiles

    if (t < 64) {
        int entry = 0; float g = 0.f;
        if (t < rows) { entry = g_bucket[e * NB + rt0 + t]; g = g_gate[entry]; }
        sEntry[t] = entry; sGate[t] = g;
    }
    if (t < 128) sBias[t] = bias[e * DM + n0 + t];
    __syncthreads();

    uint32_t dynb = smem_u32(sm_dyn);

    // loaders: t<128 -> A limbs (64 rows x 2 chunks); t>=128 -> B (128 rows)
    bool isA = (t < 128);
    const __half* src0;
    const __half* src1;
    uint32_t off0, off1;
    if (isA) {
        int lrow = t >> 1, lch = t & 1;
        size_t rb = (size_t)(sEntry[lrow] >> 1) * KP + lch * 8;
        src0 = g_Xh1 + rb;                 // a1 slot
        src1 = g_Xh2 + rb;                 // a2 slot
        off0 = A1OFF + swz(lrow, lch);
        off1 = A2OFF + swz(lrow, lch);
    } else {
        int lrow = t - 128;                // B row 0..127
        size_t rb = ((size_t)e * DM + n0 + lrow) * KP;
        src0 = g_Wh + rb;                  // chunk 0
        src1 = g_Wh + rb + 8;              // chunk 1
        off0 = BOFF + swz(lrow, 0);
        off1 = BOFF + swz(lrow, 1);
    }

    // issue one super-stage (2 subs x 2 cp16 per thread)
    auto issue_super = [&](int sup) {
        uint32_t sb = dynb + (sup % NSTG) * SSTAGE;
#pragma unroll
        for (int s = 0; s < 2; s++) {
            uint32_t ssb = sb + s * SUB;
            int ko = sup * 32 + s * 16;
            cp16(ssb + off0, src0 + ko);
            cp16(ssb + off1, src1 + ko);
        }
    };

    // prologue: supers 0..2 (one commit group each)
    issue_super(0); cp_commit();
    issue_super(1); cp_commit();
    issue_super(2); cp_commit();

    float acc[2][4][4];
#pragma unroll
    for (int i = 0; i < 2; i++)
#pragma unroll
        for (int j = 0; j < 4; j++)
#pragma unroll
            for (int q = 0; q < 4; q++) acc[i][j][q] = 0.f;

    // fragment address offsets (swizzled; +16-row steps leave swizzle additive)
    int l7 = lane & 7;
    int aRow = wm * 32 + l7 + ((lane >> 3) & 1) * 8;
    uint32_t aRowOff = swz(aRow, (lane >> 4) & 1);
    int bRow = wn * 32 + ((lane >> 4) & 1) * 8 + l7;
    uint32_t bRow4Off = swz(bRow, (lane >> 3) & 1);

    for (int i = 0; i < NSUP; i++) {
        cp_wait<2>();       // super i's group done (2 newest may pend)
        __syncthreads();    // publish super i; all warps done reading super i-1

        // refill the stage freed at iter i-1 (safe: all warps past barrier)
        if (i + 3 < NSUP) issue_super(i + 3);
        cp_commit();

        uint32_t sb = dynb + (i % NSTG) * SSTAGE;
#pragma unroll
        for (int s = 0; s < 2; s++) {
            uint32_t ssb = sb + s * SUB;

            // B fragments: 2 ldm_x4 (two tn-pairs)
            uint32_t bh[4][2];
#pragma unroll
            for (int p = 0; p < 2; p++) {
                uint32_t r4[4];
                ldm_x4(r4, ssb + BOFF + bRow4Off + p * 16 * 32);
                bh[2 * p][0] = r4[0]; bh[2 * p][1] = r4[1];
                bh[2 * p + 1][0] = r4[2]; bh[2 * p + 1][1] = r4[3];
            }

            // A fragments: both tm, both limbs (4 ldm_x4)
            uint32_t a1[2][4], a2[2][4];
#pragma unroll
            for (int tm = 0; tm < 2; tm++) {
                uint32_t aa = ssb + A1OFF + aRowOff + tm * 16 * 32;
                ldm_x4(a1[tm], aa);
                ldm_x4(a2[tm], aa + (A2OFF - A1OFF));
            }

            // pass-major issue: 8-accumulator reuse distance
#pragma unroll
            for (int tm = 0; tm < 2; tm++)
#pragma unroll
                for (int tn = 0; tn < 4; tn++)
                    MMA_F16(acc[tm][tn], a1[tm], bh[tn]);
#pragma unroll
            for (int tm = 0; tm < 2; tm++)
#pragma unroll
                for (int tn = 0; tn < 4; tn++)
                    MMA_F16(acc[tm][tn], a2[tm], bh[tn]);
        }
    }

    // epilogue: bias + gate, write to scratch
    int rq = lane >> 2, cq = (lane & 3) * 2;
#pragma unroll
    for (int tm = 0; tm < 2; tm++) {
        int r0 = wm * 32 + tm * 16 + rq;
        int r1 = r0 + 8;
#pragma unroll
        for (int tn = 0; tn < 4; tn++) {
            int cl = wn * 32 + tn * 8 + cq;
            float b0 = sBias[cl], b1 = sBias[cl + 1];
            if (r0 < rows) {
                float g = sGate[r0];
                float2 o = make_float2(g * (acc[tm][tn][0] + b0),
                                       g * (acc[tm][tn][1] + b1));
                *(float2*)(g_scratch + (size_t)sEntry[r0] * DM + n0 + cl) = o;
            }
            if (r1 < rows) {
                float g = sGate[r1];
                float2 o = make_float2(g * (acc[tm][tn][2] + b0),
                                       g * (acc[tm][tn][3] + b1));
                *(float2*)(g_scratch + (size_t)sEntry[r1] * DM + n0 + cl) = o;
            }
        }
    }
}

// ---------------------------------------------------------------------------
__global__ void guide_kernel(float* __restrict__ out) {
    __shared__ float sm[512];
    int t = threadIdx.x;
    sm[t] = g_partial[t];
    __syncthreads();
    for (int s = 256; s > 0; s >>= 1) {
        if (t < s) sm[t] += sm[t + s];
        __syncthreads();
    }
    if (t == 0) {
        float sv = sm[0] / (float)NB;
        float d = 1.f - sv;
        out[OUT_GUIDE] = d * d;
    }
}

// ---------------------------------------------------------------------------
// Streaming selection-embedding: out_sel[b, s] = sum_e iw[b,e]*selemb[b,e,s].
__global__ void __launch_bounds__(256) selemb_kernel(
    const float* __restrict__ selemb,
    float*       __restrict__ out)
{
    int warp = (blockIdx.x * 256 + threadIdx.x) >> 5;
    int lane = threadIdx.x & 31;
    int b = warp;

    float w[NE];
#pragma unroll
    for (int e = 0; e < NE; e++) w[e] = g_iw[b * NE + e];

    const float4* base = (const float4*)(selemb + (size_t)b * NE * DSEL);
    float4 acc = make_float4(0.f, 0.f, 0.f, 0.f);
#pragma unroll
    for (int e = 0; e < NE; e++) {
        float4 v = base[e * (DSEL / 4) + lane];
        acc.x += w[e] * v.x; acc.y += w[e] * v.y;
        acc.z += w[e] * v.z; acc.w += w[e] * v.w;
    }
    float* dst = out + OUT_SEL + (size_t)b * DSEL + lane * 4;
    dst[0] = acc.x; dst[1] = acc.y; dst[2] = acc.z; dst[3] = acc.w;
}

// ---------------------------------------------------------------------------
// Combine slot0 + slot1, quantize to bf16, write f32. Also resets g_count
// for the next graph replay (runs after gemm consumed the counts).
__global__ void combine_kernel(float* __restrict__ out) {
    int idx = blockIdx.x * blockDim.x + threadIdx.x;
    if (blockIdx.x == 0 && threadIdx.x < NE) g_count[threadIdx.x] = 0;
    int b   = idx >> 7;
    int m4  = (idx & 127) << 2;
    float g1 = g_gate[2 * b], g2 = g_gate[2 * b + 1];
    float4 v = make_float4(0.f, 0.f, 0.f, 0.f);
    if (g1 > 0.f) {
        float4 s = *(const float4*)(g_scratch + (size_t)(2 * b) * DM + m4);
        v.x += s.x; v.y += s.y; v.z += s.z; v.w += s.w;
    }
    if (g2 > 0.f) {
        float4 s = *(const float4*)(g_scratch + (size_t)(2 * b + 1) * DM + m4);
        v.x += s.x; v.y += s.y; v.z += s.z; v.w += s.w;
    }
    float4 o;
    o.x = __bfloat162float(__float2bfloat16(v.x));
    o.y = __bfloat162float(__float2bfloat16(v.y));
    o.z = __bfloat162float(__float2bfloat16(v.z));
    o.w = __bfloat162float(__float2bfloat16(v.w));
    ((float4*)out)[idx] = o;
}

// ---------------------------------------------------------------------------
extern "C" void kernel_launch(void* const* d_in, const int* in_sizes, int n_in,
                              void* d_out, int out_size)
{
    const float* X      = (const float*)d_in[0];
    const float* logits = (const float*)d_in[1];
    const int*   masks  = (const int*)  d_in[2];
    const float* selemb = (const float*)d_in[3];
    const float* W      = (const float*)d_in[4];
    const float* bias   = (const float*)d_in[5];
    float* out = (float*)d_out;

    cudaFuncSetAttribute(gemm_kernel,
                         cudaFuncAttributeMaxDynamicSharedMemorySize, DYNSM);

    phaseA_kernel<<<NB / 32, 1024>>>(logits, masks);                       // 1
    split_x_kernel<<<(int)(((size_t)NB * KP + 255) / 256), 256>>>(X);      // 2
    dim3 wg(KP / 32, DM / 32, NE);
    split_w_kernel<<<wg, dim3(32, 8)>>>(W);                                // 3
    dim3 g(NB / 64, DM / 128, NE);
    gemm_kernel<<<g, 256, DYNSM>>>(bias);                                  // 4 (profiled)
    guide_kernel<<<1, 512>>>(out);                                         // 5
    selemb_kernel<<<NB / 8, 256>>>(selemb, out);                           // 6
    combine_kernel<<<(NB * DM / 4) / 256, 256>>>(out);                     // 7
}

// round 16
// speedup vs baseline: 1.4249x; 1.4249x over previous
#include <cuda_runtime.h>
#include <cuda_fp16.h>
#include <cuda_bf16.h>
#include <cstdint>

#define NB   16384
#define NE   8
#define DIN  900
#define DM   512
#define DSEL 128
#define EPSF 1e-9f

#define KP     928            // 58 * 16, zero-padded K
#define NSUP   29             // super k-steps of K=32
#define NSTG   4              // super-stage pipeline depth
#define SSTAGE 24576          // bytes per super-stage (2 subs x 3 arrays x 128 x 32B)
#define SUB    12288          // per 16-K sub-block: a1 4KB | a2 4KB | b 4KB
#define A1OFF  0
#define A2OFF  4096
#define BOFF   8192
#define DYNSM  (NSTG * SSTAGE) // 98304

#define OUT_GUIDE (NB * DM)
#define OUT_SEL   (NB * DM + 1)

__device__ float g_scratch[(size_t)2 * NB * DM];     // gated per-(token,slot) outputs
__device__ int   g_bucket[NE * NB];
__device__ int   g_count[NE];                        // zero-init at load; combine resets
__device__ float g_gate[2 * NB];
__device__ float g_iw[NB * NE];                      // inactive-mixture weights
__device__ float g_partial[512];
__device__ __half g_Xh1[(size_t)NB * KP];            // X fp16 hi limb
__device__ __half g_Xh2[(size_t)NB * KP];            // X fp16 lo limb
__device__ __half g_Wh[(size_t)NE * DM * KP];        // W transposed [e][n][k], fp16

// ---------------------------------------------------------------------------
__device__ __forceinline__ uint32_t smem_u32(const void* p) {
    return (uint32_t)__cvta_generic_to_shared(p);
}
__device__ __forceinline__ void cp16(uint32_t s, const void* g) {
    asm volatile("cp.async.cg.shared.global [%0], [%1], 16;" :: "r"(s), "l"(g));
}
// .noinc: arrive against the initialized expect-count (default variant
// increments pending count first -> net zero -> deadlock; R15 lesson).
__device__ __forceinline__ void cp_mbar_arrive_noinc(uint32_t mbar) {
    asm volatile("cp.async.mbarrier.arrive.noinc.shared.b64 [%0];"
                 :: "r"(mbar) : "memory");
}
__device__ __forceinline__ void mbar_init(uint32_t mbar, uint32_t cnt) {
    asm volatile("mbarrier.init.shared.b64 [%0], %1;" :: "r"(mbar), "r"(cnt) : "memory");
}
__device__ __forceinline__ void mbar_arrive(uint32_t mbar) {
    asm volatile("mbarrier.arrive.shared.b64 _, [%0];" :: "r"(mbar) : "memory");
}
__device__ __forceinline__ void mbar_wait(uint32_t mbar, uint32_t parity) {
    asm volatile(
        "{\n\t.reg .pred P;\n\t"
        "WL_%=:\n\t"
        "mbarrier.try_wait.parity.shared.b64 P, [%0], %1, 0x989680;\n\t"
        "@P bra.uni WD_%=;\n\t"
        "bra.uni WL_%=;\n\t"
        "WD_%=:\n\t}"
        :: "r"(mbar), "r"(parity) : "memory");
}
__device__ __forceinline__ void ldm_x4(uint32_t* r, uint32_t a) {
    asm volatile("ldmatrix.sync.aligned.m8n8.x4.shared.b16 {%0,%1,%2,%3}, [%4];"
                 : "=r"(r[0]), "=r"(r[1]), "=r"(r[2]), "=r"(r[3]) : "r"(a));
}
#define MMA_F16(acc, a, b) \
    asm volatile("mma.sync.aligned.m16n8k16.row.col.f32.f16.f16.f32 " \
        "{%0,%1,%2,%3}, {%4,%5,%6,%7}, {%8,%9}, {%0,%1,%2,%3};" \
        : "+f"((acc)[0]), "+f"((acc)[1]), "+f"((acc)[2]), "+f"((acc)[3]) \
        : "r"((a)[0]), "r"((a)[1]), "r"((a)[2]), "r"((a)[3]), \
          "r"((b)[0]), "r"((b)[1]))

// swizzled offset for (row, chunk16) in a Nx32B array: kills LDSM conflicts
__device__ __forceinline__ uint32_t swz(int row, int chunk) {
    return (uint32_t)(row * 32 + (chunk ^ ((row >> 2) & 1)) * 16);
}

// ---------------------------------------------------------------------------
// Phase A lite: softmax, gates, top-2, bucketing, guide partials.
__global__ void __launch_bounds__(1024) phaseA_kernel(
    const float* __restrict__ logits,
    const int*   __restrict__ masks)
{
    __shared__ int   lcount[NE];
    __shared__ int   lbase[NE];
    __shared__ int   staging[NE][32];
    __shared__ float warpS[32];

    int tid  = threadIdx.x;
    int warp = tid >> 5;
    int lane = tid & 31;
    if (tid < NE) lcount[tid] = 0;
    __syncthreads();

    int b = blockIdx.x * 32 + warp;

    float raw[NE];
    float mx = -1e30f;
#pragma unroll
    for (int e = 0; e < NE; e++) { raw[e] = logits[b * NE + e]; mx = fmaxf(mx, raw[e]); }
    float sum = 0.f;
#pragma unroll
    for (int e = 0; e < NE; e++) { raw[e] = expf(raw[e] - mx); sum += raw[e]; }
    float inv = 1.f / sum;
    int m[NE];
#pragma unroll
    for (int e = 0; e < NE; e++) { raw[e] *= inv; m[e] = masks[b * NE + e]; }

    float w[NE]; float isum = 0.f;
#pragma unroll
    for (int e = 0; e < NE; e++) { w[e] = (m[e] == 1) ? 0.f : raw[e]; isum += w[e]; }
    float winv = 1.f / (isum + EPSF);

    float a[NE]; float srow = 0.f;
#pragma unroll
    for (int e = 0; e < NE; e++) {
        w[e] *= winv;
        a[e] = (m[e] == 1) ? raw[e] : 0.f;
        srow += a[e];
    }

    float v1 = -1.f, v2 = -1.f; int e1 = 0, e2 = 0;
#pragma unroll
    for (int e = 0; e < NE; e++) {
        if (a[e] > v1) { v2 = v1; e2 = e1; v1 = a[e]; e1 = e; }
        else if (a[e] > v2) { v2 = a[e]; e2 = e; }
    }
    float gs = 1.f / (v1 + v2 + EPSF);
    float g1 = v1 * gs, g2 = v2 * gs;

    if (lane == 0) {
#pragma unroll
        for (int e = 0; e < NE; e++) g_iw[b * NE + e] = w[e];
        g_gate[2 * b]     = g1;
        g_gate[2 * b + 1] = g2;
        if (g1 > 0.f) { int p = atomicAdd(&lcount[e1], 1); staging[e1][p] = 2 * b; }
        if (g2 > 0.f) { int p = atomicAdd(&lcount[e2], 1); staging[e2][p] = 2 * b + 1; }
        warpS[warp] = srow;
    }
    __syncthreads();
    if (tid < NE) lbase[tid] = atomicAdd(&g_count[tid], lcount[tid]);
    if (tid == 0) {
        float s = 0.f;
        for (int i = 0; i < 32; i++) s += warpS[i];
        g_partial[blockIdx.x] = s;
    }
    __syncthreads();
#pragma unroll
    for (int e = 0; e < NE; e++) {
        for (int i = tid; i < lcount[e]; i += blockDim.x)
            g_bucket[e * NB + lbase[e] + i] = staging[e][i];
    }
}

// ---------------------------------------------------------------------------
// Split X into fp16 hi/lo limbs (x = x1 + x2), vectorized: 8 elems/thread.
__global__ void split_x_kernel(const float* __restrict__ X) {
    int idx = blockIdx.x * blockDim.x + threadIdx.x;
    int b = idx / 116, j = idx % 116;     // 116 * 8 = 928 = KP
    if (b >= NB) return;
    int k0 = j * 8;
    float v[8];
    if (k0 + 8 <= DIN) {
        float4 u0 = *(const float4*)(X + (size_t)b * DIN + k0);
        float4 u1 = *(const float4*)(X + (size_t)b * DIN + k0 + 4);
        v[0] = u0.x; v[1] = u0.y; v[2] = u0.z; v[3] = u0.w;
        v[4] = u1.x; v[5] = u1.y; v[6] = u1.z; v[7] = u1.w;
    } else {
#pragma unroll
        for (int q = 0; q < 8; q++)
            v[q] = (k0 + q < DIN) ? X[(size_t)b * DIN + k0 + q] : 0.f;
    }
    __half2 h1[4], h2[4];
#pragma unroll
    for (int q = 0; q < 4; q++) {
        __half a = __float2half(v[2 * q]), c = __float2half(v[2 * q + 1]);
        h1[q] = __halves2half2(a, c);
        h2[q] = __halves2half2(__float2half(v[2 * q] - __half2float(a)),
                               __float2half(v[2 * q + 1] - __half2float(c)));
    }
    *(float4*)(g_Xh1 + (size_t)b * KP + k0) = *(float4*)h1;
    *(float4*)(g_Xh2 + (size_t)b * KP + k0) = *(float4*)h2;
}

// ---------------------------------------------------------------------------
// Transpose W[e][k][n] -> [e][n][kpad] single fp16 limb.
__global__ void split_w_kernel(const float* __restrict__ W) {
    __shared__ float tile[32][33];
    int e = blockIdx.z;
    int k0 = blockIdx.x * 32;
    int n0 = blockIdx.y * 32;
    int tx = threadIdx.x, ty = threadIdx.y;
#pragma unroll
    for (int i = 0; i < 4; i++) {
        int k = k0 + ty + i * 8;
        tile[ty + i * 8][tx] = (k < DIN) ? W[((size_t)e * DIN + k) * DM + n0 + tx] : 0.f;
    }
    __syncthreads();
#pragma unroll
    for (int i = 0; i < 4; i++) {
        int n = n0 + ty + i * 8;
        int kk = k0 + tx;
        if (kk < KP) {
            g_Wh[((size_t)e * DM + n) * KP + kk] = __float2half(tile[tx][ty + i * 8]);
        }
    }
}

// ---------------------------------------------------------------------------
// Tensor-core grouped GEMM: mma.sync fp16, 2-pass X-limb split.  (R13 tile)
// CTA tile 128x128, 8 warps (2m x 4n, 64x32 warp tiles), 2 CTAs/SM.
// Barrier-free mbarrier pipeline — full[s]/empty[s] per stage, warps free-run;
// no __syncthreads in the mainloop. Fills signal via cp.async.mbarrier.noinc.
extern __shared__ char sm_dyn[];

__global__ void __launch_bounds__(256, 2) gemm_kernel(
    const float* __restrict__ bias)
{
    int e   = blockIdx.z;
    int cnt = g_count[e];
    int rt0 = blockIdx.x * 128;
    if (rt0 >= cnt) return;
    int rows = cnt - rt0; if (rows > 128) rows = 128;
    int n0 = blockIdx.y * 128;

    __shared__ int   sEntry[128];
    __shared__ float sGate[128];
    __shared__ float sBias[128];
    __shared__ __align__(8) unsigned long long s_full[NSTG], s_empty[NSTG];

    int t = threadIdx.x;
    int wid = t >> 5, lane = t & 31;
    int wm = wid & 1, wn = wid >> 1;       // 2 x 4 warp grid

    if (t < 128) {
        int entry = 0; float g = 0.f;
        if (t < rows) { entry = g_bucket[e * NB + rt0 + t]; g = g_gate[entry]; }
        sEntry[t] = entry; sGate[t] = g;
        sBias[t]  = bias[e * DM + n0 + t];
    }
    if (t == 0) {
#pragma unroll
        for (int s = 0; s < NSTG; s++) {
            mbar_init(smem_u32(&s_full[s]), 256);
            mbar_init(smem_u32(&s_empty[s]), 256);
        }
    }
    __syncthreads();

    uint32_t dynb = smem_u32(sm_dyn);
    uint32_t fullb = smem_u32(&s_full[0]);
    uint32_t emptyb = smem_u32(&s_empty[0]);

    // per-thread cp.async sources: row = t>>1, chunk = t&1 (16B each)
    int lrow = t >> 1, lch = t & 1;
    const __half* a1Src = g_Xh1 + (size_t)(sEntry[lrow] >> 1) * KP + lch * 8;
    const __half* a2Src = g_Xh2 + (size_t)(sEntry[lrow] >> 1) * KP + lch * 8;
    const __half* bSrc  = g_Wh + ((size_t)e * DM + n0 + lrow) * KP + lch * 8;
    uint32_t smoff = swz(lrow, lch);       // swizzled 16B slot for this thread

    // issue one super-stage (2 sub-blocks, 6 cp16 per thread)
    auto issue_super = [&](int sup) {
        uint32_t sb = dynb + (sup % NSTG) * SSTAGE;
#pragma unroll
        for (int s = 0; s < 2; s++) {
            uint32_t ssb = sb + s * SUB;
            int ko = sup * 32 + s * 16;
            cp16(ssb + A1OFF + smoff, a1Src + ko);
            cp16(ssb + A2OFF + smoff, a2Src + ko);
            cp16(ssb + BOFF + smoff, bSrc + ko);
        }
    };

    // prologue: fill supers 0..2; each fill signals its full barrier
    for (int sup = 0; sup < NSTG - 1; sup++) {
        issue_super(sup);
        cp_mbar_arrive_noinc(fullb + (sup & (NSTG - 1)) * 8);
    }

    float acc[4][4][4];
#pragma unroll
    for (int i = 0; i < 4; i++)
#pragma unroll
        for (int j = 0; j < 4; j++)
#pragma unroll
            for (int q = 0; q < 4; q++) acc[i][j][q] = 0.f;

    // fragment address offsets (swizzled; +16-row steps leave swizzle additive)
    int l7 = lane & 7;
    int aRow = wm * 64 + l7 + ((lane >> 3) & 1) * 8;
    uint32_t aRowOff = swz(aRow, (lane >> 4) & 1);
    int bRow = wn * 32 + ((lane >> 4) & 1) * 8 + l7;
    uint32_t bRow4Off = swz(bRow, (lane >> 3) & 1);

    for (int i = 0; i < NSUP; i++) {
        int st = i & (NSTG - 1);
        mbar_wait(fullb + st * 8, (i >> 2) & 1);   // stage i data published

        uint32_t sb = dynb + st * SSTAGE;
#pragma unroll
        for (int s = 0; s < 2; s++) {
            uint32_t ssb = sb + s * SUB;

            // B fragments: 2 ldm_x4 (two tn-pairs)
            uint32_t bh[4][2];
#pragma unroll
            for (int p = 0; p < 2; p++) {
                uint32_t r4[4];
                ldm_x4(r4, ssb + BOFF + bRow4Off + p * 16 * 32);
                bh[2 * p][0] = r4[0]; bh[2 * p][1] = r4[1];
                bh[2 * p + 1][0] = r4[2]; bh[2 * p + 1][1] = r4[3];
            }

            // A fragments (limb1 + limb2): double-buffered across tm
            uint32_t a1[2][4], a2[2][4];
            {
                uint32_t aa = ssb + A1OFF + aRowOff;
                ldm_x4(a1[0], aa);
                ldm_x4(a2[0], aa + (A2OFF - A1OFF));
            }
#pragma unroll
            for (int tm = 0; tm < 4; tm++) {
                int cur = tm & 1;
                if (tm < 3) {
                    uint32_t aa = ssb + A1OFF + aRowOff + (tm + 1) * 16 * 32;
                    ldm_x4(a1[cur ^ 1], aa);
                    ldm_x4(a2[cur ^ 1], aa + (A2OFF - A1OFF));
                }
                // pass-major issue: consecutive MMAs -> independent accumulators
#pragma unroll
                for (int tn = 0; tn < 4; tn++)
                    MMA_F16(acc[tm][tn], a1[cur], bh[tn]);
#pragma unroll
                for (int tn = 0; tn < 4; tn++)
                    MMA_F16(acc[tm][tn], a2[cur], bh[tn]);
            }
        }
        mbar_arrive(emptyb + st * 8);              // done reading stage i

        int sup = i + NSTG - 1;
        if (sup < NSUP) {
            int es = sup & (NSTG - 1);
            if (sup >= NSTG)                        // refill: stage was read before
                mbar_wait(emptyb + es * 8, ((sup - NSTG) >> 2) & 1);
            issue_super(sup);
            cp_mbar_arrive_noinc(fullb + es * 8);
        }
    }

    // epilogue: bias + gate, write to scratch
    int rq = lane >> 2, cq = (lane & 3) * 2;
#pragma unroll
    for (int tm = 0; tm < 4; tm++) {
        int r0 = wm * 64 + tm * 16 + rq;
        int r1 = r0 + 8;
#pragma unroll
        for (int tn = 0; tn < 4; tn++) {
            int cl = wn * 32 + tn * 8 + cq;
            float b0 = sBias[cl], b1 = sBias[cl + 1];
            if (r0 < rows) {
                float g = sGate[r0];
                float2 o = make_float2(g * (acc[tm][tn][0] + b0),
                                       g * (acc[tm][tn][1] + b1));
                *(float2*)(g_scratch + (size_t)sEntry[r0] * DM + n0 + cl) = o;
            }
            if (r1 < rows) {
                float g = sGate[r1];
                float2 o = make_float2(g * (acc[tm][tn][2] + b0),
                                       g * (acc[tm][tn][3] + b1));
                *(float2*)(g_scratch + (size_t)sEntry[r1] * DM + n0 + cl) = o;
            }
        }
    }
}

// ---------------------------------------------------------------------------
__global__ void guide_kernel(float* __restrict__ out) {
    __shared__ float sm[512];
    int t = threadIdx.x;
    sm[t] = g_partial[t];
    __syncthreads();
    for (int s = 256; s > 0; s >>= 1) {
        if (t < s) sm[t] += sm[t + s];
        __syncthreads();
    }
    if (t == 0) {
        float sv = sm[0] / (float)NB;
        float d = 1.f - sv;
        out[OUT_GUIDE] = d * d;
    }
}

// ---------------------------------------------------------------------------
// Streaming selection-embedding: out_sel[b, s] = sum_e iw[b,e]*selemb[b,e,s].
__global__ void __launch_bounds__(256) selemb_kernel(
    const float* __restrict__ selemb,
    float*       __restrict__ out)
{
    int warp = (blockIdx.x * 256 + threadIdx.x) >> 5;
    int lane = threadIdx.x & 31;
    int b = warp;

    float w[NE];
#pragma unroll
    for (int e = 0; e < NE; e++) w[e] = g_iw[b * NE + e];

    const float4* base = (const float4*)(selemb + (size_t)b * NE * DSEL);
    float4 acc = make_float4(0.f, 0.f, 0.f, 0.f);
#pragma unroll
    for (int e = 0; e < NE; e++) {
        float4 v = base[e * (DSEL / 4) + lane];
        acc.x += w[e] * v.x; acc.y += w[e] * v.y;
        acc.z += w[e] * v.z; acc.w += w[e] * v.w;
    }
    float* dst = out + OUT_SEL + (size_t)b * DSEL + lane * 4;
    dst[0] = acc.x; dst[1] = acc.y; dst[2] = acc.z; dst[3] = acc.w;
}

// ---------------------------------------------------------------------------
// Combine slot0 + slot1, quantize to bf16, write f32. Also resets g_count
// for the next graph replay (runs after gemm consumed the counts).
__global__ void combine_kernel(float* __restrict__ out) {
    int idx = blockIdx.x * blockDim.x + threadIdx.x;
    if (blockIdx.x == 0 && threadIdx.x < NE) g_count[threadIdx.x] = 0;
    int b   = idx >> 7;
    int m4  = (idx & 127) << 2;
    float g1 = g_gate[2 * b], g2 = g_gate[2 * b + 1];
    float4 v = make_float4(0.f, 0.f, 0.f, 0.f);
    if (g1 > 0.f) {
        float4 s = *(const float4*)(g_scratch + (size_t)(2 * b) * DM + m4);
        v.x += s.x; v.y += s.y; v.z += s.z; v.w += s.w;
    }
    if (g2 > 0.f) {
        float4 s = *(const float4*)(g_scratch + (size_t)(2 * b + 1) * DM + m4);
        v.x += s.x; v.y += s.y; v.z += s.z; v.w += s.w;
    }
    float4 o;
    o.x = __bfloat162float(__float2bfloat16(v.x));
    o.y = __bfloat162float(__float2bfloat16(v.y));
    o.z = __bfloat162float(__float2bfloat16(v.z));
    o.w = __bfloat162float(__float2bfloat16(v.w));
    ((float4*)out)[idx] = o;
}

// ---------------------------------------------------------------------------
extern "C" void kernel_launch(void* const* d_in, const int* in_sizes, int n_in,
                              void* d_out, int out_size)
{
    const float* X      = (const float*)d_in[0];
    const float* logits = (const float*)d_in[1];
    const int*   masks  = (const int*)  d_in[2];
    const float* selemb = (const float*)d_in[3];
    const float* W      = (const float*)d_in[4];
    const float* bias   = (const float*)d_in[5];
    float* out = (float*)d_out;

    cudaFuncSetAttribute(gemm_kernel,
                         cudaFuncAttributeMaxDynamicSharedMemorySize, DYNSM);

    phaseA_kernel<<<NB / 32, 1024>>>(logits, masks);                       // 1
    split_x_kernel<<<(NB * 116 + 255) / 256, 256>>>(X);                    // 2
    dim3 wg(KP / 32, DM / 32, NE);
    split_w_kernel<<<wg, dim3(32, 8)>>>(W);                                // 3
    dim3 g(NB / 128, DM / 128, NE);
    gemm_kernel<<<g, 256, DYNSM>>>(bias);                                  // 4 (profiled)
    guide_kernel<<<1, 512>>>(out);                                         // 5
    selemb_kernel<<<NB / 8, 256>>>(selemb, out);                           // 6
    combine_kernel<<<(NB * DM / 4) / 256, 256>>>(out);                     // 7
}